// round 15
// baseline (speedup 1.0000x reference)
#include <cuda_runtime.h>
#include <math.h>

#define TT 2048
#define NROWS 128
#define NF 20
#define LK 769
#define PADL 384
#define SIGP_LEN 2816   /* TT + 2*384 */
#define NBINS 18
#define PI_F 3.14159265358979f

// -------------------- scratch (no allocs allowed) --------------------
__device__ float g_sigp[NROWS * SIGP_LEN];            // 1.44 MB
__device__ float g_filt[NROWS * NF * TT];             // 21 MB
__device__ unsigned char g_bin[NROWS * 10 * TT];      // 2.6 MB
__device__ float g_amp[NROWS * 10 * TT];              // 10.5 MB
__device__ int   g_cnt[NROWS * 10 * NBINS];
__device__ unsigned short g_perm[NROWS * 10 * TT];    // 5.2 MB (counting sort)
__device__ float g_twr[512], g_twi[512];

// -------------------- 0) twiddle precompute --------------------
__global__ void tw_kernel() {
    int t = threadIdx.x;
    float ang = -2.f * PI_F * (float)t / 2048.f;
    g_twr[t] = cosf(ang);
    g_twi[t] = sinf(ang);
}

// -------------------- 1) reflect pad (effective pad 384/side) ------------------
__global__ void pad_kernel(const float* __restrict__ x) {
    int row = blockIdx.x;
    const float* xr = x + row * TT;
    float* o = g_sigp + row * SIGP_LEN;
    for (int j = threadIdx.x; j < SIGP_LEN; j += blockDim.x) {
        int i = j - PADL;
        int src = (i < 0) ? -i : ((i >= TT) ? (2 * TT - 2 - i) : i);
        o[j] = xr[src];
    }
}

// -------------------- 2) FIR conv, nonzero-trimmed, sliding register window ----
__global__ __launch_bounds__(256) void conv_kernel(const float* __restrict__ Kf) {
    __shared__ __align__(16) float ssig[2832];
    __shared__ __align__(16) float sk[784];
    __shared__ int s_lo, s_hi;
    int f = blockIdx.x, row = blockIdx.y;
    int tid = threadIdx.x;

    for (int j = tid; j < 2832; j += 256)
        ssig[j] = (j < SIGP_LEN) ? g_sigp[row * SIGP_LEN + j] : 0.f;
    for (int j = tid; j < 784; j += 256)
        sk[j] = (j < LK) ? Kf[f * LK + j] : 0.f;
    if (tid == 0) { s_lo = LK; s_hi = 0; }
    __syncthreads();

    int llo = LK, lhi = 0;
    for (int j = tid; j < LK; j += 256)
        if (sk[j] != 0.f) { if (j < llo) llo = j; if (j > lhi) lhi = j; }
    atomicMin(&s_lo, llo);
    atomicMax(&s_hi, lhi);
    __syncthreads();

    int l0 = s_lo & ~7;
    int l1 = (s_hi + 8) & ~7;     // exclusive; zero taps are free

    int t0 = tid * 8;             // 8 consecutive outputs per thread
    float acc[8];
#pragma unroll
    for (int r = 0; r < 8; r++) acc[r] = 0.f;

    float s[16];
    {
        float4 v0 = *(const float4*)&ssig[t0 + l0];
        float4 v1 = *(const float4*)&ssig[t0 + l0 + 4];
        s[0]=v0.x; s[1]=v0.y; s[2]=v0.z; s[3]=v0.w;
        s[4]=v1.x; s[5]=v1.y; s[6]=v1.z; s[7]=v1.w;
    }
    for (int l = l0; l < l1; l += 8) {
        float4 v2 = *(const float4*)&ssig[t0 + l + 8];
        float4 v3 = *(const float4*)&ssig[t0 + l + 12];
        s[8]=v2.x;  s[9]=v2.y;  s[10]=v2.z; s[11]=v2.w;
        s[12]=v3.x; s[13]=v3.y; s[14]=v3.z; s[15]=v3.w;
#pragma unroll
        for (int j = 0; j < 8; j++) {
            float kv = sk[l + j];
#pragma unroll
            for (int r = 0; r < 8; r++) acc[r] = fmaf(s[j + r], kv, acc[r]);
        }
#pragma unroll
        for (int i = 0; i < 8; i++) s[i] = s[i + 8];
    }
    float* o = &g_filt[(row * NF + f) * TT + t0];
    *(float4*)&o[0] = make_float4(acc[0], acc[1], acc[2], acc[3]);
    *(float4*)&o[4] = make_float4(acc[4], acc[5], acc[6], acc[7]);
}

// -------------------- 3) 2048-pt radix-8 Stockham, ping-pong, fused ------------
#define IDX(i) ((i) + ((i) >> 3))

__device__ __forceinline__ void bfly8(const float* xr, const float* xi,
                                      float* yr, float* yi) {
    const float C = 0.70710678118654752f;
    float a0r=xr[0]+xr[4], a0i=xi[0]+xi[4];
    float a1r=xr[0]-xr[4], a1i=xi[0]-xi[4];
    float a2r=xr[2]+xr[6], a2i=xi[2]+xi[6];
    float a3r=xr[2]-xr[6], a3i=xi[2]-xi[6];
    float a4r=xr[1]+xr[5], a4i=xi[1]+xi[5];
    float a5r=xr[1]-xr[5], a5i=xi[1]-xi[5];
    float a6r=xr[3]+xr[7], a6i=xi[3]+xi[7];
    float a7r=xr[3]-xr[7], a7i=xi[3]-xi[7];
    float t3r =  a3i, t3i = -a3r;
    float t7r =  a7i, t7i = -a7r;
    float b0r=a0r+a2r, b0i=a0i+a2i;
    float b1r=a0r-a2r, b1i=a0i-a2i;
    float b2r=a1r+t3r, b2i=a1i+t3i;
    float b3r=a1r-t3r, b3i=a1i-t3i;
    float b4r=a4r+a6r, b4i=a4i+a6i;
    float b5r=a4r-a6r, b5i=a4i-a6i;
    float b6r=a5r+t7r, b6i=a5i+t7i;
    float b7r=a5r-t7r, b7i=a5i-t7i;
    float o1r =  C*(b6r + b6i), o1i =  C*(b6i - b6r);
    float o3r =  C*(b7i - b7r), o3i = -C*(b7r + b7i);
    yr[0]=b0r+b4r; yi[0]=b0i+b4i;
    yr[4]=b0r-b4r; yi[4]=b0i-b4i;
    yr[1]=b2r+o1r; yi[1]=b2i+o1i;
    yr[5]=b2r-o1r; yi[5]=b2i-o1i;
    yr[2]=b1r+b5i; yi[2]=b1i-b5r;
    yr[6]=b1r-b5i; yi[6]=b1i+b5r;
    yr[3]=b3r+o3r; yi[3]=b3i+o3i;
    yr[7]=b3r-o3r; yi[7]=b3i-o3i;
}

template<int MODE>
__device__ __forceinline__ void stage8(
    const float* sr, const float* si,
    const float* __restrict__ gx, const float* __restrict__ gy,
    float* dr, float* di, int s, int tid,
    const float* twr, const float* twi)
{
    int b = tid;
    int k1 = b & ~(s - 1);
    int d  = b & (s - 1);
    int base = 8 * k1 + d;

    float xr[8], xi[8];
#pragma unroll
    for (int m = 0; m < 8; m++) {
        int k = b + m * 256;
        if (MODE == 1) { xr[m] = gx[k]; xi[m] = gy[k]; }
        else if (MODE == 0) { xr[m] = sr[IDX(k)]; xi[m] = si[IDX(k)]; }
        else {
            float sg = (k == 0 || k == 1024) ? 0.f : (k < 1024 ? 1.f : -1.f);
            float zr = sr[IDX(k)], zi = si[IDX(k)];
            xr[m] = sg * zi;  xi[m] = sg * zr;
        }
    }
    float yr[8], yi[8];
    bfly8(xr, xi, yr, yi);

    float w1r = twr[k1], w1i = twi[k1];
    float w2r = w1r*w1r - w1i*w1i, w2i = 2.f*w1r*w1i;
    float w4r = w2r*w2r - w2i*w2i, w4i = 2.f*w2r*w2i;
    float w3r = w2r*w1r - w2i*w1i, w3i = w2r*w1i + w2i*w1r;
    float w5r = w4r*w1r - w4i*w1i, w5i = w4r*w1i + w4i*w1r;
    float w6r = w3r*w3r - w3i*w3i, w6i = 2.f*w3r*w3i;
    float w7r = w4r*w3r - w4i*w3i, w7i = w4r*w3i + w4i*w3r;

    dr[IDX(base)]       = yr[0];                    di[IDX(base)]       = yi[0];
    dr[IDX(base + s)]   = yr[1]*w1r - yi[1]*w1i;    di[IDX(base + s)]   = yr[1]*w1i + yi[1]*w1r;
    dr[IDX(base + 2*s)] = yr[2]*w2r - yi[2]*w2i;    di[IDX(base + 2*s)] = yr[2]*w2i + yi[2]*w2r;
    dr[IDX(base + 3*s)] = yr[3]*w3r - yi[3]*w3i;    di[IDX(base + 3*s)] = yr[3]*w3i + yi[3]*w3r;
    dr[IDX(base + 4*s)] = yr[4]*w4r - yi[4]*w4i;    di[IDX(base + 4*s)] = yr[4]*w4i + yi[4]*w4r;
    dr[IDX(base + 5*s)] = yr[5]*w5r - yi[5]*w5i;    di[IDX(base + 5*s)] = yr[5]*w5i + yi[5]*w5r;
    dr[IDX(base + 6*s)] = yr[6]*w6r - yi[6]*w6i;    di[IDX(base + 6*s)] = yr[6]*w6i + yi[6]*w6r;
    dr[IDX(base + 7*s)] = yr[7]*w7r - yi[7]*w7i;    di[IDX(base + 7*s)] = yr[7]*w7i + yi[7]*w7r;
}

__device__ __forceinline__ void stage4_smem(const float* sr, const float* si,
                                            float* dr, float* di, int tid) {
#pragma unroll
    for (int u = 0; u < 2; u++) {
        int b = tid + u * 256;
        float r0 = sr[IDX(b)],        i0 = si[IDX(b)];
        float r1 = sr[IDX(b + 512)],  i1 = si[IDX(b + 512)];
        float r2 = sr[IDX(b + 1024)], i2 = si[IDX(b + 1024)];
        float r3 = sr[IDX(b + 1536)], i3 = si[IDX(b + 1536)];
        float apc_r = r0+r2, apc_i = i0+i2;
        float amc_r = r0-r2, amc_i = i0-i2;
        float bpd_r = r1+r3, bpd_i = i1+i3;
        float bmd_r = r1-r3, bmd_i = i1-i3;
        dr[IDX(b)]        = apc_r + bpd_r;  di[IDX(b)]        = apc_i + bpd_i;
        dr[IDX(b +  512)] = amc_r + bmd_i;  di[IDX(b +  512)] = amc_i - bmd_r;
        dr[IDX(b + 1024)] = apc_r - bpd_r;  di[IDX(b + 1024)] = apc_i - bpd_i;
        dr[IDX(b + 1536)] = amc_r - bmd_i;  di[IDX(b + 1536)] = amc_i + bmd_r;
    }
}

__global__ __launch_bounds__(256, 3) void hilbert_kernel() {
    __shared__ __align__(16) float Ar[2304], Ai[2304], Br[2304], Bi[2304];
    __shared__ float twr[256], twi[256];
    __shared__ int hist[NBINS];
    int tid = threadIdx.x;
    int pb = blockIdx.x;            // 0..1279
    int row = pb / 10, fp = pb % 10;

    twr[tid] = g_twr[tid];
    twi[tid] = g_twi[tid];
    if (tid < NBINS) hist[tid] = 0;

    const float* xs = &g_filt[(row * NF + fp) * TT];        // pha-band signal
    const float* ys = &g_filt[(row * NF + fp + 10) * TT];   // amp-band signal
    __syncthreads();

    // FFT1
    stage8<1>(0, 0, xs, ys, Ar, Ai, 1, tid, twr, twi);   __syncthreads();
    stage8<0>(Ar, Ai, 0, 0, Br, Bi, 8, tid, twr, twi);   __syncthreads();
    stage8<0>(Br, Bi, 0, 0, Ar, Ai, 64, tid, twr, twi);  __syncthreads();
    stage4_smem(Ar, Ai, Br, Bi, tid);                    __syncthreads();
    // FFT2 (multiplier fused into stage0 reads)
    stage8<2>(Br, Bi, 0, 0, Ar, Ai, 1, tid, twr, twi);   __syncthreads();
    stage8<0>(Ar, Ai, 0, 0, Br, Bi, 8, tid, twr, twi);   __syncthreads();
    stage8<0>(Br, Bi, 0, 0, Ar, Ai, 64, tid, twr, twi);  __syncthreads();

    const float scale = 1.f / 2048.f;
    const float B_OVER_2PI = (float)NBINS / (2.f * PI_F);
    int orow = row * 10 + fp;
#pragma unroll
    for (int u = 0; u < 2; u++) {
        int b = tid + u * 256;
        float r0 = Ar[IDX(b)],        i0 = Ai[IDX(b)];
        float r1 = Ar[IDX(b + 512)],  i1 = Ai[IDX(b + 512)];
        float r2 = Ar[IDX(b + 1024)], i2 = Ai[IDX(b + 1024)];
        float r3 = Ar[IDX(b + 1536)], i3 = Ai[IDX(b + 1536)];
        float apc_r = r0+r2, apc_i = i0+i2;
        float amc_r = r0-r2, amc_i = i0-i2;
        float bpd_r = r1+r3, bpd_i = i1+i3;
        float bmd_r = r1-r3, bmd_i = i1-i3;
        float outr[4], outi[4];
        int   idx[4];
        outr[0] = apc_r + bpd_r;  outi[0] = apc_i + bpd_i;  idx[0] = b;
        outr[1] = amc_r + bmd_i;  outi[1] = amc_i - bmd_r;  idx[1] = b + 512;
        outr[2] = apc_r - bpd_r;  outi[2] = apc_i - bpd_i;  idx[2] = b + 1024;
        outr[3] = amc_r - bmd_i;  outi[3] = amc_i + bmd_r;  idx[3] = b + 1536;
#pragma unroll
        for (int q = 0; q < 4; q++) {
            int j = idx[q];
            float hx =  outr[q] * scale;
            float hy = -outi[q] * scale;
            float re = xs[j];
            float ph = atan2f(hx, re);
            int bin = (int)floorf((ph + PI_F) * B_OVER_2PI);
            bin = bin < 0 ? 0 : (bin > NBINS - 1 ? NBINS - 1 : bin);
            g_bin[orow * TT + j] = (unsigned char)bin;
            atomicAdd(&hist[bin], 1);
            float ay = ys[j];
            g_amp[orow * TT + j] = sqrtf(ay * ay + hy * hy);
        }
    }
    __syncthreads();
    if (tid < NBINS) g_cnt[orow * NBINS + tid] = hist[tid];
}

// -------------------- 4a) counting-sort permutation per pha row ---------------
__global__ __launch_bounds__(256) void perm_build_kernel() {
    __shared__ int offs[NBINS + 1];
    __shared__ int counter[NBINS];
    int prow = blockIdx.x;
    int tid = threadIdx.x;
    if (tid == 0) {
        int acc = 0;
        for (int b = 0; b < NBINS; b++) {
            offs[b] = acc;
            acc += g_cnt[prow * NBINS + b];
        }
        offs[NBINS] = acc;   // == 2048
    }
    __syncthreads();
    if (tid < NBINS) counter[tid] = offs[tid];
    __syncthreads();
    const unsigned char* bp = g_bin + prow * TT;
    unsigned short* pp = g_perm + prow * TT;
    for (int j = tid; j < TT; j += 256) {
        int b = bp[j];
        int pos = atomicAdd(&counter[b], 1);
        pp[pos] = (unsigned short)j;
    }
}

// -------------------- 4b) modulation index v4: sorted gather ------------------
// Block = (p_, z=(bc,sp)): one pha row's sorted permutation, 10 amp rows.
// Bins are contiguous in sorted order -> each thread's 16-run crosses <=2
// boundaries -> ~2 shared atomics/thread/row (vs 16 scatter atomics in v3).
__global__ __launch_bounds__(128) void mi_kernel(float* __restrict__ out) {
    __shared__ unsigned short perm_s[TT];       // 4 KB
    __shared__ unsigned char  sbin[TT];         // 2 KB (bin id at sorted pos)
    __shared__ __align__(16) float samp[TT];    // 8 KB
    __shared__ int offs[NBINS + 1];
    __shared__ float acc[NBINS];
    int tid = threadIdx.x;
    int p_ = blockIdx.x, z = blockIdx.y;
    int bc = z >> 2, sp = z & 3;
    int mp = p_ * 4 + sp;
    int prow = (bc * 4 + mp / 10) * 10 + (mp % 10);

    if (tid == 0) {
        int a = 0;
        for (int b = 0; b < NBINS; b++) { offs[b] = a; a += g_cnt[prow * NBINS + b]; }
        offs[NBINS] = TT;
    }
    // load perm row (vectorized as uint)
    {
        const unsigned* src = (const unsigned*)(g_perm + prow * TT);
        unsigned* dst = (unsigned*)perm_s;
        for (int j = tid; j < TT / 2; j += 128) dst[j] = src[j];
    }
    __syncthreads();
    // bin id per sorted position (monotonic scan per thread)
    {
        int b = 0;
        for (int j = tid; j < TT; j += 128) {
            while (j >= offs[b + 1]) b++;
            sbin[j] = (unsigned char)b;
        }
    }

    int j0 = tid * 16;
    for (int ai = 0; ai < 10; ai++) {
        int ma = ai * 4 + sp;
        int arow = (bc * 4 + ma / 10) * 10 + (ma % 10);
        const float4* asrc = (const float4*)(g_amp + arow * TT);
        __syncthreads();                 // protect acc/samp from previous iter
        for (int j = tid; j < TT / 4; j += 128)
            *(float4*)&samp[4 * j] = asrc[j];
        if (tid < NBINS) acc[tid] = 0.f;
        __syncthreads();

        // gather 16 sorted-contiguous samples, sum runs, flush at boundaries
        int cur = sbin[j0];
        float partial = 0.f;
#pragma unroll 4
        for (int i = 0; i < 16; i++) {
            int j = j0 + i;
            float v = samp[perm_s[j]];
            int b = sbin[j];
            if (b != cur) {
                atomicAdd(&acc[cur], partial);
                partial = v; cur = b;
            } else {
                partial += v;
            }
        }
        atomicAdd(&acc[cur], partial);
        __syncthreads();

        if (tid == 0) {
            float mean[NBINS];
            float msum = 0.f;
#pragma unroll
            for (int b = 0; b < NBINS; b++) {
                float c = (float)(offs[b + 1] - offs[b]);
                float m = acc[b] / fmaxf(c, 1.f);
                mean[b] = m; msum += m;
            }
            msum = fmaxf(msum, 1e-12f);
            float ent = 0.f;
#pragma unroll
            for (int b = 0; b < NBINS; b++) {
                float pb = mean[b] / msum;
                ent += pb * logf(fmaxf(pb, 1e-12f));
            }
            const float LOGN = logf((float)NBINS);
            float mi = (LOGN + ent) / LOGN;
            atomicAdd(&out[(bc * 10 + p_) * 10 + ai], 0.25f * mi);
        }
    }
}

// -------------------- launch --------------------
extern "C" void kernel_launch(void* const* d_in, const int* in_sizes, int n_in,
                              void* d_out, int out_size) {
    const float* x = (const float*)d_in[0];
    const float* K = (const float*)d_in[1];
    if (n_in >= 2 && in_sizes[0] == NF * LK) {   // robust to metadata order
        const float* t = x; x = K; K = t;
    }
    tw_kernel<<<1, 512>>>();
    pad_kernel<<<NROWS, 256>>>(x);
    conv_kernel<<<dim3(NF, NROWS), 256>>>(K);
    hilbert_kernel<<<NROWS * 10, 256>>>();
    perm_build_kernel<<<NROWS * 10, 256>>>();
    cudaMemsetAsync(d_out, 0, (size_t)out_size * sizeof(float));
    mi_kernel<<<dim3(10, 128), 128>>>((float*)d_out);
}

// round 16
// speedup vs baseline: 1.2382x; 1.2382x over previous
#include <cuda_runtime.h>
#include <math.h>

#define TT 2048
#define NROWS 128
#define NF 20
#define LK 769
#define PADL 384
#define SIGP_LEN 2816   /* TT + 2*384 */
#define NBINS 18
#define PI_F 3.14159265358979f

typedef unsigned long long ull;

// -------------------- scratch (no allocs allowed) --------------------
__device__ float g_sigp[NROWS * SIGP_LEN];            // 1.44 MB
__device__ float g_filt[NROWS * NF * TT];             // 21 MB
__device__ unsigned char g_bin[NROWS * 10 * TT];      // 2.6 MB
__device__ float g_amp[NROWS * 10 * TT];              // 10.5 MB
__device__ int   g_cnt[NROWS * 10 * NBINS];
__device__ float g_twr[512], g_twi[512];

// -------------------- f32x2 helpers --------------------
__device__ __forceinline__ void fma2(ull& d, ull a, ull b) {
    asm("fma.rn.f32x2 %0, %1, %2, %0;" : "+l"(d) : "l"(a), "l"(b));
}
__device__ __forceinline__ float lo32(ull v) { return __uint_as_float((unsigned)v); }
__device__ __forceinline__ float hi32(ull v) { return __uint_as_float((unsigned)(v >> 32)); }

// -------------------- 0) twiddle precompute --------------------
__global__ void tw_kernel() {
    int t = threadIdx.x;
    float ang = -2.f * PI_F * (float)t / 2048.f;
    g_twr[t] = cosf(ang);
    g_twi[t] = sinf(ang);
}

// -------------------- 1) reflect pad (effective pad 384/side) ------------------
__global__ void pad_kernel(const float* __restrict__ x) {
    int row = blockIdx.x;
    const float* xr = x + row * TT;
    float* o = g_sigp + row * SIGP_LEN;
    for (int j = threadIdx.x; j < SIGP_LEN; j += blockDim.x) {
        int i = j - PADL;
        int src = (i < 0) ? -i : ((i >= TT) ? (2 * TT - 2 - i) : i);
        o[j] = xr[src];
    }
}

// -------------------- 2) FIR conv v3: (t, t+1024) output pairs, FFMA2 ----------
// Q[u] = (sigp[u], sigp[u+1024]) -> both halves of the row share tap offsets,
// so every packed operand is an aligned unit-stride 64-bit word. Pad every 16
// elements keeps half-warp LDS.64 phases (near-)conflict-free.
#define QN 1808
#define QI(u) ((u) + ((u) >> 4))

__global__ __launch_bounds__(256) void conv_kernel(const float* __restrict__ Kf) {
    __shared__ __align__(16) float2 qs[QI(QN - 1) + 2];   // ~15.4 KB
    __shared__ __align__(16) float2 skp[784];             // taps duplicated (k,k)
    __shared__ int s_lo, s_hi;
    int f = blockIdx.x, row = blockIdx.y;
    int tid = threadIdx.x;

    const float* sp = g_sigp + row * SIGP_LEN;
    for (int u = tid; u < QN; u += 256) {
        float lo = sp[u];
        int u2 = u + 1024;
        float hi = (u2 < SIGP_LEN) ? sp[u2] : 0.f;
        qs[QI(u)] = make_float2(lo, hi);
    }
    for (int j = tid; j < 784; j += 256) {
        float k = (j < LK) ? Kf[f * LK + j] : 0.f;
        skp[j] = make_float2(k, k);
    }
    if (tid == 0) { s_lo = LK; s_hi = 0; }
    __syncthreads();

    int llo = LK, lhi = 0;
    for (int j = tid; j < LK; j += 256)
        if (skp[j].x != 0.f) { if (j < llo) llo = j; if (j > lhi) lhi = j; }
    atomicMin(&s_lo, llo);
    atomicMax(&s_hi, lhi);
    __syncthreads();

    int l0 = s_lo & ~7;
    int l1 = (s_hi + 8) & ~7;     // exclusive; zero taps are free

    int t0 = tid * 4;             // outputs t0..t0+3 (lo) and +1024 (hi)
    ull A[4];
#pragma unroll
    for (int p = 0; p < 4; p++) A[p] = 0ull;

    const ull* q = (const ull*)qs;
    const ull* kp = (const ull*)skp;

    ull W[11];
#pragma unroll
    for (int m = 0; m < 3; m++) W[m] = q[QI(t0 + l0 + m)];

    for (int l = l0; l < l1; l += 8) {
#pragma unroll
        for (int m = 3; m < 11; m++) W[m] = q[QI(t0 + l + m)];
#pragma unroll
        for (int j = 0; j < 8; j++) {
            ull kk = kp[l + j];
            fma2(A[0], W[j],     kk);
            fma2(A[1], W[j + 1], kk);
            fma2(A[2], W[j + 2], kk);
            fma2(A[3], W[j + 3], kk);
        }
#pragma unroll
        for (int m = 0; m < 3; m++) W[m] = W[m + 8];
    }

    float* o = &g_filt[(row * NF + f) * TT + t0];
    *(float4*)&o[0]    = make_float4(lo32(A[0]), lo32(A[1]), lo32(A[2]), lo32(A[3]));
    *(float4*)&o[1024] = make_float4(hi32(A[0]), hi32(A[1]), hi32(A[2]), hi32(A[3]));
}

// -------------------- 3) 2048-pt radix-8 Stockham, ping-pong, fused ------------
#define IDX(i) ((i) + ((i) >> 3))

__device__ __forceinline__ void bfly8(const float* xr, const float* xi,
                                      float* yr, float* yi) {
    const float C = 0.70710678118654752f;
    float a0r=xr[0]+xr[4], a0i=xi[0]+xi[4];
    float a1r=xr[0]-xr[4], a1i=xi[0]-xi[4];
    float a2r=xr[2]+xr[6], a2i=xi[2]+xi[6];
    float a3r=xr[2]-xr[6], a3i=xi[2]-xi[6];
    float a4r=xr[1]+xr[5], a4i=xi[1]+xi[5];
    float a5r=xr[1]-xr[5], a5i=xi[1]-xi[5];
    float a6r=xr[3]+xr[7], a6i=xi[3]+xi[7];
    float a7r=xr[3]-xr[7], a7i=xi[3]-xi[7];
    float t3r =  a3i, t3i = -a3r;
    float t7r =  a7i, t7i = -a7r;
    float b0r=a0r+a2r, b0i=a0i+a2i;
    float b1r=a0r-a2r, b1i=a0i-a2i;
    float b2r=a1r+t3r, b2i=a1i+t3i;
    float b3r=a1r-t3r, b3i=a1i-t3i;
    float b4r=a4r+a6r, b4i=a4i+a6i;
    float b5r=a4r-a6r, b5i=a4i-a6i;
    float b6r=a5r+t7r, b6i=a5i+t7i;
    float b7r=a5r-t7r, b7i=a5i-t7i;
    float o1r =  C*(b6r + b6i), o1i =  C*(b6i - b6r);
    float o3r =  C*(b7i - b7r), o3i = -C*(b7r + b7i);
    yr[0]=b0r+b4r; yi[0]=b0i+b4i;
    yr[4]=b0r-b4r; yi[4]=b0i-b4i;
    yr[1]=b2r+o1r; yi[1]=b2i+o1i;
    yr[5]=b2r-o1r; yi[5]=b2i-o1i;
    yr[2]=b1r+b5i; yi[2]=b1i-b5r;
    yr[6]=b1r-b5i; yi[6]=b1i+b5r;
    yr[3]=b3r+o3r; yi[3]=b3i+o3i;
    yr[7]=b3r-o3r; yi[7]=b3i-o3i;
}

template<int MODE>
__device__ __forceinline__ void stage8(
    const float* sr, const float* si,
    const float* __restrict__ gx, const float* __restrict__ gy,
    float* dr, float* di, int s, int tid,
    const float* twr, const float* twi)
{
    int b = tid;
    int k1 = b & ~(s - 1);
    int d  = b & (s - 1);
    int base = 8 * k1 + d;

    float xr[8], xi[8];
#pragma unroll
    for (int m = 0; m < 8; m++) {
        int k = b + m * 256;
        if (MODE == 1) { xr[m] = gx[k]; xi[m] = gy[k]; }
        else if (MODE == 0) { xr[m] = sr[IDX(k)]; xi[m] = si[IDX(k)]; }
        else {
            float sg = (k == 0 || k == 1024) ? 0.f : (k < 1024 ? 1.f : -1.f);
            float zr = sr[IDX(k)], zi = si[IDX(k)];
            xr[m] = sg * zi;  xi[m] = sg * zr;
        }
    }
    float yr[8], yi[8];
    bfly8(xr, xi, yr, yi);

    float w1r = twr[k1], w1i = twi[k1];
    float w2r = w1r*w1r - w1i*w1i, w2i = 2.f*w1r*w1i;
    float w4r = w2r*w2r - w2i*w2i, w4i = 2.f*w2r*w2i;
    float w3r = w2r*w1r - w2i*w1i, w3i = w2r*w1i + w2i*w1r;
    float w5r = w4r*w1r - w4i*w1i, w5i = w4r*w1i + w4i*w1r;
    float w6r = w3r*w3r - w3i*w3i, w6i = 2.f*w3r*w3i;
    float w7r = w4r*w3r - w4i*w3i, w7i = w4r*w3i + w4i*w3r;

    dr[IDX(base)]       = yr[0];                    di[IDX(base)]       = yi[0];
    dr[IDX(base + s)]   = yr[1]*w1r - yi[1]*w1i;    di[IDX(base + s)]   = yr[1]*w1i + yi[1]*w1r;
    dr[IDX(base + 2*s)] = yr[2]*w2r - yi[2]*w2i;    di[IDX(base + 2*s)] = yr[2]*w2i + yi[2]*w2r;
    dr[IDX(base + 3*s)] = yr[3]*w3r - yi[3]*w3i;    di[IDX(base + 3*s)] = yr[3]*w3i + yi[3]*w3r;
    dr[IDX(base + 4*s)] = yr[4]*w4r - yi[4]*w4i;    di[IDX(base + 4*s)] = yr[4]*w4i + yi[4]*w4r;
    dr[IDX(base + 5*s)] = yr[5]*w5r - yi[5]*w5i;    di[IDX(base + 5*s)] = yr[5]*w5i + yi[5]*w5r;
    dr[IDX(base + 6*s)] = yr[6]*w6r - yi[6]*w6i;    di[IDX(base + 6*s)] = yr[6]*w6i + yi[6]*w6r;
    dr[IDX(base + 7*s)] = yr[7]*w7r - yi[7]*w7i;    di[IDX(base + 7*s)] = yr[7]*w7i + yi[7]*w7r;
}

__device__ __forceinline__ void stage4_smem(const float* sr, const float* si,
                                            float* dr, float* di, int tid) {
#pragma unroll
    for (int u = 0; u < 2; u++) {
        int b = tid + u * 256;
        float r0 = sr[IDX(b)],        i0 = si[IDX(b)];
        float r1 = sr[IDX(b + 512)],  i1 = si[IDX(b + 512)];
        float r2 = sr[IDX(b + 1024)], i2 = si[IDX(b + 1024)];
        float r3 = sr[IDX(b + 1536)], i3 = si[IDX(b + 1536)];
        float apc_r = r0+r2, apc_i = i0+i2;
        float amc_r = r0-r2, amc_i = i0-i2;
        float bpd_r = r1+r3, bpd_i = i1+i3;
        float bmd_r = r1-r3, bmd_i = i1-i3;
        dr[IDX(b)]        = apc_r + bpd_r;  di[IDX(b)]        = apc_i + bpd_i;
        dr[IDX(b +  512)] = amc_r + bmd_i;  di[IDX(b +  512)] = amc_i - bmd_r;
        dr[IDX(b + 1024)] = apc_r - bpd_r;  di[IDX(b + 1024)] = apc_i - bpd_i;
        dr[IDX(b + 1536)] = amc_r - bmd_i;  di[IDX(b + 1536)] = amc_i + bmd_r;
    }
}

__global__ __launch_bounds__(256, 3) void hilbert_kernel() {
    __shared__ __align__(16) float Ar[2304], Ai[2304], Br[2304], Bi[2304];
    __shared__ float twr[256], twi[256];
    __shared__ int hist[NBINS];
    int tid = threadIdx.x;
    int pb = blockIdx.x;            // 0..1279
    int row = pb / 10, fp = pb % 10;

    twr[tid] = g_twr[tid];
    twi[tid] = g_twi[tid];
    if (tid < NBINS) hist[tid] = 0;

    const float* xs = &g_filt[(row * NF + fp) * TT];        // pha-band signal
    const float* ys = &g_filt[(row * NF + fp + 10) * TT];   // amp-band signal
    __syncthreads();

    // FFT1
    stage8<1>(0, 0, xs, ys, Ar, Ai, 1, tid, twr, twi);   __syncthreads();
    stage8<0>(Ar, Ai, 0, 0, Br, Bi, 8, tid, twr, twi);   __syncthreads();
    stage8<0>(Br, Bi, 0, 0, Ar, Ai, 64, tid, twr, twi);  __syncthreads();
    stage4_smem(Ar, Ai, Br, Bi, tid);                    __syncthreads();
    // FFT2 (multiplier fused into stage0 reads)
    stage8<2>(Br, Bi, 0, 0, Ar, Ai, 1, tid, twr, twi);   __syncthreads();
    stage8<0>(Ar, Ai, 0, 0, Br, Bi, 8, tid, twr, twi);   __syncthreads();
    stage8<0>(Br, Bi, 0, 0, Ar, Ai, 64, tid, twr, twi);  __syncthreads();

    const float scale = 1.f / 2048.f;
    const float B_OVER_2PI = (float)NBINS / (2.f * PI_F);
    int orow = row * 10 + fp;
#pragma unroll
    for (int u = 0; u < 2; u++) {
        int b = tid + u * 256;
        float r0 = Ar[IDX(b)],        i0 = Ai[IDX(b)];
        float r1 = Ar[IDX(b + 512)],  i1 = Ai[IDX(b + 512)];
        float r2 = Ar[IDX(b + 1024)], i2 = Ai[IDX(b + 1024)];
        float r3 = Ar[IDX(b + 1536)], i3 = Ai[IDX(b + 1536)];
        float apc_r = r0+r2, apc_i = i0+i2;
        float amc_r = r0-r2, amc_i = i0-i2;
        float bpd_r = r1+r3, bpd_i = i1+i3;
        float bmd_r = r1-r3, bmd_i = i1-i3;
        float outr[4], outi[4];
        int   idx[4];
        outr[0] = apc_r + bpd_r;  outi[0] = apc_i + bpd_i;  idx[0] = b;
        outr[1] = amc_r + bmd_i;  outi[1] = amc_i - bmd_r;  idx[1] = b + 512;
        outr[2] = apc_r - bpd_r;  outi[2] = apc_i - bpd_i;  idx[2] = b + 1024;
        outr[3] = amc_r - bmd_i;  outi[3] = amc_i + bmd_r;  idx[3] = b + 1536;
#pragma unroll
        for (int q = 0; q < 4; q++) {
            int j = idx[q];
            float hx =  outr[q] * scale;
            float hy = -outi[q] * scale;
            float re = xs[j];
            float ph = atan2f(hx, re);
            int bin = (int)floorf((ph + PI_F) * B_OVER_2PI);
            bin = bin < 0 ? 0 : (bin > NBINS - 1 ? NBINS - 1 : bin);
            g_bin[orow * TT + j] = (unsigned char)bin;
            atomicAdd(&hist[bin], 1);
            float ay = ys[j];
            g_amp[orow * TT + j] = sqrtf(ay * ay + hy * hy);
        }
    }
    __syncthreads();
    if (tid < NBINS) g_cnt[orow * NBINS + tid] = hist[tid];
}

// -------------------- 4) modulation index v3 (reverted known-best) -------------
__global__ __launch_bounds__(128) void mi_kernel(float* __restrict__ out) {
    __shared__ float red[90 * 32];     // 11520 B
    __shared__ float ssum[90];
    int tid = threadIdx.x;
    int lane = tid & 31;
    int ag = blockIdx.x, p_ = blockIdx.y, z = blockIdx.z;
    int bc = z >> 2, sp = z & 3;
    int mp = p_ * 4 + sp;
    int prow = (bc * 4 + mp / 10) * 10 + (mp % 10);
    const unsigned char* bp = g_bin + prow * TT;

    const float* ap[5];
#pragma unroll
    for (int ai = 0; ai < 5; ai++) {
        int ma = (ag * 5 + ai) * 4 + sp;
        int arow = (bc * 4 + ma / 10) * 10 + (ma % 10);
        ap[ai] = g_amp + arow * TT;
    }

    for (int j = tid; j < 90 * 32; j += 128) red[j] = 0.f;
    __syncthreads();

    int t0 = tid * 16;  // 16 contiguous samples per thread
#pragma unroll
    for (int c = 0; c < 4; c++) {
        uchar4 b4 = *(const uchar4*)(bp + t0 + c * 4);
        int i0 = (int)b4.x * 32 + lane;
        int i1 = (int)b4.y * 32 + lane;
        int i2 = (int)b4.z * 32 + lane;
        int i3 = (int)b4.w * 32 + lane;
#pragma unroll
        for (int ai = 0; ai < 5; ai++) {
            float4 v = *(const float4*)(ap[ai] + t0 + c * 4);
            int base = ai * (18 * 32);
            atomicAdd(&red[base + i0], v.x);
            atomicAdd(&red[base + i1], v.y);
            atomicAdd(&red[base + i2], v.z);
            atomicAdd(&red[base + i3], v.w);
        }
    }
    __syncthreads();

    if (tid < 90) {
        float v0 = 0.f, v1 = 0.f;
        int base = tid * 32;
#pragma unroll
        for (int i = 0; i < 32; i += 2) {
            v0 += red[base + ((tid + i) & 31)];
            v1 += red[base + ((tid + i + 1) & 31)];
        }
        ssum[tid] = v0 + v1;
    }
    __syncthreads();

    if (tid < 5) {
        int a = tid;
        float mean[NBINS];
        float msum = 0.f;
#pragma unroll
        for (int b = 0; b < NBINS; b++) {
            float v = ssum[a * 18 + b];
            float c = (float)g_cnt[prow * NBINS + b];
            float m = v / fmaxf(c, 1.f);
            mean[b] = m; msum += m;
        }
        msum = fmaxf(msum, 1e-12f);
        float ent = 0.f;
#pragma unroll
        for (int b = 0; b < NBINS; b++) {
            float pb = mean[b] / msum;
            ent += pb * logf(fmaxf(pb, 1e-12f));
        }
        const float LOGN = logf((float)NBINS);
        float mi = (LOGN + ent) / LOGN;
        int a_ = ag * 5 + a;
        atomicAdd(&out[(bc * 10 + p_) * 10 + a_], 0.25f * mi);
    }
}

// -------------------- launch --------------------
extern "C" void kernel_launch(void* const* d_in, const int* in_sizes, int n_in,
                              void* d_out, int out_size) {
    const float* x = (const float*)d_in[0];
    const float* K = (const float*)d_in[1];
    if (n_in >= 2 && in_sizes[0] == NF * LK) {   // robust to metadata order
        const float* t = x; x = K; K = t;
    }
    tw_kernel<<<1, 512>>>();
    pad_kernel<<<NROWS, 256>>>(x);
    conv_kernel<<<dim3(NF, NROWS), 256>>>(K);
    hilbert_kernel<<<NROWS * 10, 256>>>();
    cudaMemsetAsync(d_out, 0, (size_t)out_size * sizeof(float));
    mi_kernel<<<dim3(2, 10, 128), 128>>>((float*)d_out);
}

// round 17
// speedup vs baseline: 1.4600x; 1.1792x over previous
#include <cuda_runtime.h>
#include <math.h>

#define TT 2048
#define NROWS 128
#define NF 20
#define LK 769
#define PADL 384
#define SIGP_LEN 2816   /* TT + 2*384 */
#define NBINS 18
#define PI_F 3.14159265358979f

// -------------------- scratch (no allocs allowed) --------------------
__device__ float g_sigp[NROWS * SIGP_LEN];            // 1.44 MB
__device__ float g_filt[NROWS * NF * TT];             // 21 MB
__device__ unsigned char g_bin[NROWS * 10 * TT];      // 2.6 MB
__device__ float g_amp[NROWS * 10 * TT];              // 10.5 MB
__device__ int   g_cnt[NROWS * 10 * NBINS];
__device__ float g_twr[512], g_twi[512];

// -------------------- 0) twiddle precompute --------------------
__global__ void tw_kernel() {
    int t = threadIdx.x;
    float ang = -2.f * PI_F * (float)t / 2048.f;
    g_twr[t] = cosf(ang);
    g_twi[t] = sinf(ang);
}

// -------------------- 1) reflect pad (effective pad 384/side) ------------------
__global__ void pad_kernel(const float* __restrict__ x) {
    int row = blockIdx.x;
    const float* xr = x + row * TT;
    float* o = g_sigp + row * SIGP_LEN;
    for (int j = threadIdx.x; j < SIGP_LEN; j += blockDim.x) {
        int i = j - PADL;
        int src = (i < 0) ? -i : ((i >= TT) ? (2 * TT - 2 - i) : i);
        o[j] = xr[src];
    }
}

// -------------------- 2) FIR conv, nonzero-trimmed, sliding register window ----
// (scalar version — measured at ~45us, near the 3-reg FFMA floor of ~39us;
//  all three FFMA2 packings regressed, permanently rejected)
__global__ __launch_bounds__(256) void conv_kernel(const float* __restrict__ Kf) {
    __shared__ __align__(16) float ssig[2832];
    __shared__ __align__(16) float sk[784];
    __shared__ int s_lo, s_hi;
    int f = blockIdx.x, row = blockIdx.y;
    int tid = threadIdx.x;

    for (int j = tid; j < 2832; j += 256)
        ssig[j] = (j < SIGP_LEN) ? g_sigp[row * SIGP_LEN + j] : 0.f;
    for (int j = tid; j < 784; j += 256)
        sk[j] = (j < LK) ? Kf[f * LK + j] : 0.f;
    if (tid == 0) { s_lo = LK; s_hi = 0; }
    __syncthreads();

    int llo = LK, lhi = 0;
    for (int j = tid; j < LK; j += 256)
        if (sk[j] != 0.f) { if (j < llo) llo = j; if (j > lhi) lhi = j; }
    atomicMin(&s_lo, llo);
    atomicMax(&s_hi, lhi);
    __syncthreads();

    int l0 = s_lo & ~7;
    int l1 = (s_hi + 8) & ~7;     // exclusive; zero taps are free

    int t0 = tid * 8;             // 8 consecutive outputs per thread
    float acc[8];
#pragma unroll
    for (int r = 0; r < 8; r++) acc[r] = 0.f;

    float s[16];
    {
        float4 v0 = *(const float4*)&ssig[t0 + l0];
        float4 v1 = *(const float4*)&ssig[t0 + l0 + 4];
        s[0]=v0.x; s[1]=v0.y; s[2]=v0.z; s[3]=v0.w;
        s[4]=v1.x; s[5]=v1.y; s[6]=v1.z; s[7]=v1.w;
    }
    for (int l = l0; l < l1; l += 8) {
        float4 v2 = *(const float4*)&ssig[t0 + l + 8];
        float4 v3 = *(const float4*)&ssig[t0 + l + 12];
        s[8]=v2.x;  s[9]=v2.y;  s[10]=v2.z; s[11]=v2.w;
        s[12]=v3.x; s[13]=v3.y; s[14]=v3.z; s[15]=v3.w;
#pragma unroll
        for (int j = 0; j < 8; j++) {
            float kv = sk[l + j];
#pragma unroll
            for (int r = 0; r < 8; r++) acc[r] = fmaf(s[j + r], kv, acc[r]);
        }
#pragma unroll
        for (int i = 0; i < 8; i++) s[i] = s[i + 8];
    }
    float* o = &g_filt[(row * NF + f) * TT + t0];
    *(float4*)&o[0] = make_float4(acc[0], acc[1], acc[2], acc[3]);
    *(float4*)&o[4] = make_float4(acc[4], acc[5], acc[6], acc[7]);
}

// -------------------- 3) 2048-pt radix-8 Stockham, ping-pong, fused ------------
#define IDX(i) ((i) + ((i) >> 3))

__device__ __forceinline__ void bfly8(const float* xr, const float* xi,
                                      float* yr, float* yi) {
    const float C = 0.70710678118654752f;
    float a0r=xr[0]+xr[4], a0i=xi[0]+xi[4];
    float a1r=xr[0]-xr[4], a1i=xi[0]-xi[4];
    float a2r=xr[2]+xr[6], a2i=xi[2]+xi[6];
    float a3r=xr[2]-xr[6], a3i=xi[2]-xi[6];
    float a4r=xr[1]+xr[5], a4i=xi[1]+xi[5];
    float a5r=xr[1]-xr[5], a5i=xi[1]-xi[5];
    float a6r=xr[3]+xr[7], a6i=xi[3]+xi[7];
    float a7r=xr[3]-xr[7], a7i=xi[3]-xi[7];
    float t3r =  a3i, t3i = -a3r;
    float t7r =  a7i, t7i = -a7r;
    float b0r=a0r+a2r, b0i=a0i+a2i;
    float b1r=a0r-a2r, b1i=a0i-a2i;
    float b2r=a1r+t3r, b2i=a1i+t3i;
    float b3r=a1r-t3r, b3i=a1i-t3i;
    float b4r=a4r+a6r, b4i=a4i+a6i;
    float b5r=a4r-a6r, b5i=a4i-a6i;
    float b6r=a5r+t7r, b6i=a5i+t7i;
    float b7r=a5r-t7r, b7i=a5i-t7i;
    float o1r =  C*(b6r + b6i), o1i =  C*(b6i - b6r);
    float o3r =  C*(b7i - b7r), o3i = -C*(b7r + b7i);
    yr[0]=b0r+b4r; yi[0]=b0i+b4i;
    yr[4]=b0r-b4r; yi[4]=b0i-b4i;
    yr[1]=b2r+o1r; yi[1]=b2i+o1i;
    yr[5]=b2r-o1r; yi[5]=b2i-o1i;
    yr[2]=b1r+b5i; yi[2]=b1i-b5r;
    yr[6]=b1r-b5i; yi[6]=b1i+b5r;
    yr[3]=b3r+o3r; yi[3]=b3i+o3i;
    yr[7]=b3r-o3r; yi[7]=b3i-o3i;
}

template<int MODE>
__device__ __forceinline__ void stage8(
    const float* sr, const float* si,
    const float* __restrict__ gx, const float* __restrict__ gy,
    float* dr, float* di, int s, int tid,
    const float* twr, const float* twi)
{
    int b = tid;
    int k1 = b & ~(s - 1);
    int d  = b & (s - 1);
    int base = 8 * k1 + d;

    float xr[8], xi[8];
#pragma unroll
    for (int m = 0; m < 8; m++) {
        int k = b + m * 256;
        if (MODE == 1) { xr[m] = gx[k]; xi[m] = gy[k]; }
        else if (MODE == 0) { xr[m] = sr[IDX(k)]; xi[m] = si[IDX(k)]; }
        else {
            float sg = (k == 0 || k == 1024) ? 0.f : (k < 1024 ? 1.f : -1.f);
            float zr = sr[IDX(k)], zi = si[IDX(k)];
            xr[m] = sg * zi;  xi[m] = sg * zr;
        }
    }
    float yr[8], yi[8];
    bfly8(xr, xi, yr, yi);

    float w1r = twr[k1], w1i = twi[k1];
    float w2r = w1r*w1r - w1i*w1i, w2i = 2.f*w1r*w1i;
    float w4r = w2r*w2r - w2i*w2i, w4i = 2.f*w2r*w2i;
    float w3r = w2r*w1r - w2i*w1i, w3i = w2r*w1i + w2i*w1r;
    float w5r = w4r*w1r - w4i*w1i, w5i = w4r*w1i + w4i*w1r;
    float w6r = w3r*w3r - w3i*w3i, w6i = 2.f*w3r*w3i;
    float w7r = w4r*w3r - w4i*w3i, w7i = w4r*w3i + w4i*w3r;

    dr[IDX(base)]       = yr[0];                    di[IDX(base)]       = yi[0];
    dr[IDX(base + s)]   = yr[1]*w1r - yi[1]*w1i;    di[IDX(base + s)]   = yr[1]*w1i + yi[1]*w1r;
    dr[IDX(base + 2*s)] = yr[2]*w2r - yi[2]*w2i;    di[IDX(base + 2*s)] = yr[2]*w2i + yi[2]*w2r;
    dr[IDX(base + 3*s)] = yr[3]*w3r - yi[3]*w3i;    di[IDX(base + 3*s)] = yr[3]*w3i + yi[3]*w3r;
    dr[IDX(base + 4*s)] = yr[4]*w4r - yi[4]*w4i;    di[IDX(base + 4*s)] = yr[4]*w4i + yi[4]*w4r;
    dr[IDX(base + 5*s)] = yr[5]*w5r - yi[5]*w5i;    di[IDX(base + 5*s)] = yr[5]*w5i + yi[5]*w5r;
    dr[IDX(base + 6*s)] = yr[6]*w6r - yi[6]*w6i;    di[IDX(base + 6*s)] = yr[6]*w6i + yi[6]*w6r;
    dr[IDX(base + 7*s)] = yr[7]*w7r - yi[7]*w7i;    di[IDX(base + 7*s)] = yr[7]*w7i + yi[7]*w7r;
}

__device__ __forceinline__ void stage4_smem(const float* sr, const float* si,
                                            float* dr, float* di, int tid) {
#pragma unroll
    for (int u = 0; u < 2; u++) {
        int b = tid + u * 256;
        float r0 = sr[IDX(b)],        i0 = si[IDX(b)];
        float r1 = sr[IDX(b + 512)],  i1 = si[IDX(b + 512)];
        float r2 = sr[IDX(b + 1024)], i2 = si[IDX(b + 1024)];
        float r3 = sr[IDX(b + 1536)], i3 = si[IDX(b + 1536)];
        float apc_r = r0+r2, apc_i = i0+i2;
        float amc_r = r0-r2, amc_i = i0-i2;
        float bpd_r = r1+r3, bpd_i = i1+i3;
        float bmd_r = r1-r3, bmd_i = i1-i3;
        dr[IDX(b)]        = apc_r + bpd_r;  di[IDX(b)]        = apc_i + bpd_i;
        dr[IDX(b +  512)] = amc_r + bmd_i;  di[IDX(b +  512)] = amc_i - bmd_r;
        dr[IDX(b + 1024)] = apc_r - bpd_r;  di[IDX(b + 1024)] = apc_i - bpd_i;
        dr[IDX(b + 1536)] = amc_r - bmd_i;  di[IDX(b + 1536)] = amc_i + bmd_r;
    }
}

__global__ __launch_bounds__(256, 3) void hilbert_kernel() {
    __shared__ __align__(16) float Ar[2304], Ai[2304], Br[2304], Bi[2304];
    __shared__ float twr[256], twi[256];
    __shared__ int hist[NBINS];
    int tid = threadIdx.x;
    int pb = blockIdx.x;            // 0..1279
    int row = pb / 10, fp = pb % 10;

    twr[tid] = g_twr[tid];
    twi[tid] = g_twi[tid];
    if (tid < NBINS) hist[tid] = 0;

    const float* xs = &g_filt[(row * NF + fp) * TT];        // pha-band signal
    const float* ys = &g_filt[(row * NF + fp + 10) * TT];   // amp-band signal
    __syncthreads();

    // FFT1
    stage8<1>(0, 0, xs, ys, Ar, Ai, 1, tid, twr, twi);   __syncthreads();
    stage8<0>(Ar, Ai, 0, 0, Br, Bi, 8, tid, twr, twi);   __syncthreads();
    stage8<0>(Br, Bi, 0, 0, Ar, Ai, 64, tid, twr, twi);  __syncthreads();
    stage4_smem(Ar, Ai, Br, Bi, tid);                    __syncthreads();
    // FFT2 (multiplier fused into stage0 reads)
    stage8<2>(Br, Bi, 0, 0, Ar, Ai, 1, tid, twr, twi);   __syncthreads();
    stage8<0>(Ar, Ai, 0, 0, Br, Bi, 8, tid, twr, twi);   __syncthreads();
    stage8<0>(Br, Bi, 0, 0, Ar, Ai, 64, tid, twr, twi);  __syncthreads();

    const float scale = 1.f / 2048.f;
    const float B_OVER_2PI = (float)NBINS / (2.f * PI_F);
    int orow = row * 10 + fp;
#pragma unroll
    for (int u = 0; u < 2; u++) {
        int b = tid + u * 256;
        float r0 = Ar[IDX(b)],        i0 = Ai[IDX(b)];
        float r1 = Ar[IDX(b + 512)],  i1 = Ai[IDX(b + 512)];
        float r2 = Ar[IDX(b + 1024)], i2 = Ai[IDX(b + 1024)];
        float r3 = Ar[IDX(b + 1536)], i3 = Ai[IDX(b + 1536)];
        float apc_r = r0+r2, apc_i = i0+i2;
        float amc_r = r0-r2, amc_i = i0-i2;
        float bpd_r = r1+r3, bpd_i = i1+i3;
        float bmd_r = r1-r3, bmd_i = i1-i3;
        float outr[4], outi[4];
        int   idx[4];
        outr[0] = apc_r + bpd_r;  outi[0] = apc_i + bpd_i;  idx[0] = b;
        outr[1] = amc_r + bmd_i;  outi[1] = amc_i - bmd_r;  idx[1] = b + 512;
        outr[2] = apc_r - bpd_r;  outi[2] = apc_i - bpd_i;  idx[2] = b + 1024;
        outr[3] = amc_r - bmd_i;  outi[3] = amc_i + bmd_r;  idx[3] = b + 1536;
#pragma unroll
        for (int q = 0; q < 4; q++) {
            int j = idx[q];
            float hx =  outr[q] * scale;
            float hy = -outi[q] * scale;
            float re = xs[j];
            float ph = atan2f(hx, re);
            int bin = (int)floorf((ph + PI_F) * B_OVER_2PI);
            bin = bin < 0 ? 0 : (bin > NBINS - 1 ? NBINS - 1 : bin);
            g_bin[orow * TT + j] = (unsigned char)bin;
            atomicAdd(&hist[bin], 1);
            float ay = ys[j];
            g_amp[orow * TT + j] = sqrtf(ay * ay + hy * hy);
        }
    }
    __syncthreads();
    if (tid < NBINS) g_cnt[orow * NBINS + tid] = hist[tid];
}

// -------------------- 4) modulation index v3.1: run-merged atomics -------------
// Same structure as v3 (known-best), but phase bins are slowly varying:
// adjacent samples share a bin with prob ~0.58 (band-avg). Compute the 3
// adjacency flags per uchar4 ONCE (shared across 5 amp bands) and chain-merge,
// flushing an atomic only at run boundaries. ATOMS spread-addr cost is
// per-active-lane, so predicated-off flushes are free -> ~1.75x fewer
// lane-atomics on the binding pipe.
__global__ __launch_bounds__(128) void mi_kernel(float* __restrict__ out) {
    __shared__ float red[90 * 32];     // 11520 B
    __shared__ float ssum[90];
    int tid = threadIdx.x;
    int lane = tid & 31;
    int ag = blockIdx.x, p_ = blockIdx.y, z = blockIdx.z;
    int bc = z >> 2, sp = z & 3;
    int mp = p_ * 4 + sp;
    int prow = (bc * 4 + mp / 10) * 10 + (mp % 10);
    const unsigned char* bp = g_bin + prow * TT;

    const float* ap[5];
#pragma unroll
    for (int ai = 0; ai < 5; ai++) {
        int ma = (ag * 5 + ai) * 4 + sp;
        int arow = (bc * 4 + ma / 10) * 10 + (ma % 10);
        ap[ai] = g_amp + arow * TT;
    }

    for (int j = tid; j < 90 * 32; j += 128) red[j] = 0.f;
    __syncthreads();

    int t0 = tid * 16;  // 16 contiguous samples per thread
#pragma unroll
    for (int c = 0; c < 4; c++) {
        uchar4 b4 = *(const uchar4*)(bp + t0 + c * 4);
        int i0 = (int)b4.x * 32 + lane;
        int i1 = (int)b4.y * 32 + lane;
        int i2 = (int)b4.z * 32 + lane;
        int i3 = (int)b4.w * 32 + lane;
        bool e01 = (b4.x == b4.y);
        bool e12 = (b4.y == b4.z);
        bool e23 = (b4.z == b4.w);
#pragma unroll
        for (int ai = 0; ai < 5; ai++) {
            float4 v = *(const float4*)(ap[ai] + t0 + c * 4);
            float* base = red + ai * (18 * 32);
            float s = v.x;
            if (!e01) { atomicAdd(base + i0, s); s = 0.f; }
            s += v.y;
            if (!e12) { atomicAdd(base + i1, s); s = 0.f; }
            s += v.z;
            if (!e23) { atomicAdd(base + i2, s); s = 0.f; }
            s += v.w;
            atomicAdd(base + i3, s);
        }
    }
    __syncthreads();

    if (tid < 90) {
        float v0 = 0.f, v1 = 0.f;
        int base = tid * 32;
#pragma unroll
        for (int i = 0; i < 32; i += 2) {
            v0 += red[base + ((tid + i) & 31)];
            v1 += red[base + ((tid + i + 1) & 31)];
        }
        ssum[tid] = v0 + v1;
    }
    __syncthreads();

    if (tid < 5) {
        int a = tid;
        float mean[NBINS];
        float msum = 0.f;
#pragma unroll
        for (int b = 0; b < NBINS; b++) {
            float v = ssum[a * 18 + b];
            float c = (float)g_cnt[prow * NBINS + b];
            float m = v / fmaxf(c, 1.f);
            mean[b] = m; msum += m;
        }
        msum = fmaxf(msum, 1e-12f);
        float ent = 0.f;
#pragma unroll
        for (int b = 0; b < NBINS; b++) {
            float pb = mean[b] / msum;
            ent += pb * logf(fmaxf(pb, 1e-12f));
        }
        const float LOGN = logf((float)NBINS);
        float mi = (LOGN + ent) / LOGN;
        int a_ = ag * 5 + a;
        atomicAdd(&out[(bc * 10 + p_) * 10 + a_], 0.25f * mi);
    }
}

// -------------------- launch --------------------
extern "C" void kernel_launch(void* const* d_in, const int* in_sizes, int n_in,
                              void* d_out, int out_size) {
    const float* x = (const float*)d_in[0];
    const float* K = (const float*)d_in[1];
    if (n_in >= 2 && in_sizes[0] == NF * LK) {   // robust to metadata order
        const float* t = x; x = K; K = t;
    }
    tw_kernel<<<1, 512>>>();
    pad_kernel<<<NROWS, 256>>>(x);
    conv_kernel<<<dim3(NF, NROWS), 256>>>(K);
    hilbert_kernel<<<NROWS * 10, 256>>>();
    cudaMemsetAsync(d_out, 0, (size_t)out_size * sizeof(float));
    mi_kernel<<<dim3(2, 10, 128), 128>>>((float*)d_out);
}